// round 4
// baseline (speedup 1.0000x reference)
#include <cuda_runtime.h>
#include <cfloat>
#include <cstdint>

#define Bn  8
#define Ls  3136      // 56*56
#define Cn  64
#define HID 32
#define KN  30
#define NV  (Bn*Ls)   // 25088 global vertices/edges
#define NS  256       // sample columns per row (every 12th)
#define CCAP 1024     // candidate capacity per row

// ---------------- device scratch (static globals; no allocations) ----------------
__device__ float    g_sq  [NV];
__device__ float    g_sd2 [(size_t)NV*NS];      // sampled distances (25.7 MB)
__device__ unsigned g_thr [NV];                 // per-row flipped-key threshold (+margin)
__device__ int      g_ccnt[NV];                 // candidate counters
__device__ uint2    g_cand[(size_t)NV*CCAP];    // candidate (key, col) pairs (205 MB)
__device__ int      g_nbr [(size_t)NV*KN];      // per-edge neighbor lists (sample-local idx)
__device__ int      g_dvi [NV];                 // vertex in-degree (counts)
__device__ int      g_off [NV];                 // CSR offsets
__device__ int      g_cnt [NV];                 // CSR fill cursors
__device__ int      g_adj [(size_t)NV*KN];      // CSR: edges incident to each vertex
__device__ float    g_h1  [(size_t)NV*HID];
__device__ float    g_y1  [(size_t)NV*HID];
__device__ float    g_o1  [(size_t)NV*HID];
__device__ float    g_h2  [(size_t)NV*Cn];
__device__ float    g_y2  [(size_t)NV*Cn];

#define BN_SCALE 0.99999500003749969f
#define FLIPU(u) ((u) ^ ((unsigned)(((int)(u)) >> 31) | 0x80000000u))

// ---------------- kernel 1: row squared norms + zero counters ----------------
__global__ void sq_kernel(const float* __restrict__ x) {
    int tid = threadIdx.x;
    int gv = blockIdx.x * 8 + (tid >> 5);
    int lane = tid & 31;
    const float* p = x + (size_t)gv * Cn;
    float a = p[lane] * p[lane] + p[lane + 32] * p[lane + 32];
    #pragma unroll
    for (int off = 16; off; off >>= 1) a += __shfl_down_sync(0xffffffffu, a, off);
    if (lane == 0) g_sq[gv] = a;
    int t = blockIdx.x * 256 + tid;
    if (t < NV) { g_cnt[t] = 0; g_dvi[t] = 0; g_ccnt[t] = 0; }
}

// ---------------- kernel 2: sampled distances (rows x 256 sample cols) ----------------
__global__ void __launch_bounds__(64) sample_kernel(const float* __restrict__ x) {
    int s = blockIdx.z;
    int sB = s * Ls;
    const float* A  = x + (size_t)sB * Cn;
    const float* sq = g_sq + sB;
    int i0 = blockIdx.y << 6, q0 = blockIdx.x << 6;

    __shared__ __align__(16) float Ast[64][68];
    __shared__ __align__(16) float Bst[64][68];
    int tid = threadIdx.x;

    for (int f = tid; f < 1024; f += 64) {
        int m = f >> 4, kq = (f & 15) << 2;
        float4 av = *(const float4*)(A + (size_t)(i0 + m) * Cn + kq);
        Ast[kq + 0][m] = av.x; Ast[kq + 1][m] = av.y; Ast[kq + 2][m] = av.z; Ast[kq + 3][m] = av.w;
        float4 bv = *(const float4*)(A + (size_t)(12 * (q0 + m)) * Cn + kq);
        Bst[kq + 0][m] = bv.x; Bst[kq + 1][m] = bv.y; Bst[kq + 2][m] = bv.z; Bst[kq + 3][m] = bv.w;
    }
    __syncthreads();

    int m0 = (tid >> 3) << 3;
    int n0 = (tid & 7) << 3;
    float acc[8][8];
    #pragma unroll
    for (int r = 0; r < 8; r++)
        #pragma unroll
        for (int c = 0; c < 8; c++) acc[r][c] = 0.f;

    #pragma unroll 8
    for (int k = 0; k < 64; k++) {
        float a[8], b[8];
        *(float4*)(a)     = *(const float4*)&Ast[k][m0];
        *(float4*)(a + 4) = *(const float4*)&Ast[k][m0 + 4];
        *(float4*)(b)     = *(const float4*)&Bst[k][n0];
        *(float4*)(b + 4) = *(const float4*)&Bst[k][n0 + 4];
        #pragma unroll
        for (int r = 0; r < 8; r++)
            #pragma unroll
            for (int c = 0; c < 8; c++) acc[r][c] = fmaf(a[r], b[c], acc[r][c]);
    }

    float sqi[8], sqj[8];
    #pragma unroll
    for (int r = 0; r < 8; r++) sqi[r] = sq[i0 + m0 + r];
    #pragma unroll
    for (int c = 0; c < 8; c++) sqj[c] = sq[12 * (q0 + n0 + c)];
    #pragma unroll
    for (int r = 0; r < 8; r++) {
        float* orow = g_sd2 + (size_t)(sB + i0 + m0 + r) * NS + q0 + n0;
        #pragma unroll
        for (int c = 0; c < 8; c++) {
            float d = sqi[r] + sqj[c] - 2.f * acc[r][c];
            orow[c] = d;
        }
    }
}

// ---------------- kernel 3: per-row threshold = 30th smallest sampled (+margin) --------
__global__ void __launch_bounds__(256) thr_kernel() {
    int gv = blockIdx.x;
    __shared__ unsigned us[NS];
    int tid = threadIdx.x;
    unsigned u = FLIPU(__float_as_uint(g_sd2[(size_t)gv * NS + tid]));
    us[tid] = u;
    __syncthreads();
    int rank = 0;
    #pragma unroll 8
    for (int j = 0; j < NS; j++) {
        unsigned uj = us[j];
        rank += (uj < u) || (uj == u && j < tid);
    }
    if (rank == KN - 1) g_thr[gv] = u + 64u;   // +64 ulp safety margin
}

// ---------------- kernel 4: fused distance + candidate filter (symmetric tiles) -------
__global__ void __launch_bounds__(64) dist_kernel(const float* __restrict__ x) {
    int ti = blockIdx.y, tj = blockIdx.x;
    if (ti > tj) return;
    int s = blockIdx.z;
    int sB = s * Ls;
    const float* A  = x + (size_t)sB * Cn;
    const float* sq = g_sq + sB;
    int i0 = ti << 6, j0 = tj << 6;

    __shared__ __align__(16) float Ast[64][68];
    __shared__ __align__(16) float Bst[64][68];
    int tid = threadIdx.x;

    for (int f = tid; f < 1024; f += 64) {
        int m = f >> 4, kq = (f & 15) << 2;
        float4 av = *(const float4*)(A + (size_t)(i0 + m) * Cn + kq);
        Ast[kq + 0][m] = av.x; Ast[kq + 1][m] = av.y; Ast[kq + 2][m] = av.z; Ast[kq + 3][m] = av.w;
        float4 bv = *(const float4*)(A + (size_t)(j0 + m) * Cn + kq);
        Bst[kq + 0][m] = bv.x; Bst[kq + 1][m] = bv.y; Bst[kq + 2][m] = bv.z; Bst[kq + 3][m] = bv.w;
    }
    __syncthreads();

    int m0 = (tid >> 3) << 3;
    int n0 = (tid & 7) << 3;
    float acc[8][8];
    #pragma unroll
    for (int r = 0; r < 8; r++)
        #pragma unroll
        for (int c = 0; c < 8; c++) acc[r][c] = 0.f;

    #pragma unroll 8
    for (int k = 0; k < 64; k++) {
        float a[8], b[8];
        *(float4*)(a)     = *(const float4*)&Ast[k][m0];
        *(float4*)(a + 4) = *(const float4*)&Ast[k][m0 + 4];
        *(float4*)(b)     = *(const float4*)&Bst[k][n0];
        *(float4*)(b + 4) = *(const float4*)&Bst[k][n0 + 4];
        #pragma unroll
        for (int r = 0; r < 8; r++)
            #pragma unroll
            for (int c = 0; c < 8; c++) acc[r][c] = fmaf(a[r], b[c], acc[r][c]);
    }

    float sqi[8], sqj[8];
    unsigned thri[8], thrj[8];
    #pragma unroll
    for (int r = 0; r < 8; r++) { sqi[r] = sq[i0 + m0 + r]; thri[r] = g_thr[sB + i0 + m0 + r]; }
    #pragma unroll
    for (int c = 0; c < 8; c++) { sqj[c] = sq[j0 + n0 + c]; thrj[c] = g_thr[sB + j0 + n0 + c]; }

    bool offd = (ti != tj);
    #pragma unroll
    for (int r = 0; r < 8; r++) {
        int gi = sB + i0 + m0 + r;
        #pragma unroll
        for (int c = 0; c < 8; c++) {
            float d = sqi[r] + sqj[c] - 2.f * acc[r][c];
            unsigned u = FLIPU(__float_as_uint(d));
            if (u <= thri[r]) {
                int p = atomicAdd(&g_ccnt[gi], 1);
                if (p < CCAP) g_cand[(size_t)gi * CCAP + p] = make_uint2(u, (unsigned)(j0 + n0 + c));
            }
            if (offd && u <= thrj[c]) {
                int gj = sB + j0 + n0 + c;
                int p = atomicAdd(&g_ccnt[gj], 1);
                if (p < CCAP) g_cand[(size_t)gj * CCAP + p] = make_uint2(u, (unsigned)(i0 + m0 + r));
            }
        }
    }
}

// ---------------- kernel 5: exact top-30 among candidates ----------------
__global__ void __launch_bounds__(256) select_kernel(const float* __restrict__ x) {
    int s = blockIdx.y, i = blockIdx.x;
    int sB = s * Ls;
    int gv = sB + i;
    int tid = threadIdx.x;
    __shared__ __align__(16) unsigned sbuf[3264];   // union: ull[1024] | u32 su[3136] + ft[64]
    int cnt = g_ccnt[gv];
    int* nout = g_nbr + (size_t)gv * KN;
    int* dv = g_dvi + sB;

    if (cnt <= CCAP) {
        unsigned long long* sk = (unsigned long long*)sbuf;
        for (int t = tid; t < cnt; t += 256) {
            uint2 cc = g_cand[(size_t)gv * CCAP + t];
            sk[t] = ((unsigned long long)cc.x << 32) | (unsigned long long)cc.y;
        }
        __syncthreads();
        for (int t = tid; t < cnt; t += 256) {
            unsigned long long K = sk[t];
            int rank = 0;
            for (int j = 0; j < cnt; j++) rank += (sk[j] < K);
            if (rank < KN) {
                int idx = (int)(K & 0xffffffffull);
                nout[rank] = idx;
                atomicAdd(&dv[idx], 1);
            }
        }
    } else {
        // rare exact fallback: recompute the full row and rank-select
        float* ft = (float*)&sbuf[3136];
        if (tid < 64) ft[tid] = x[(size_t)gv * Cn + tid];
        __syncthreads();
        float sqi = g_sq[gv];
        for (int t = tid; t < Ls; t += 256) {
            const float* pr = x + (size_t)(sB + t) * Cn;
            float acc = 0.f;
            #pragma unroll 16
            for (int k = 0; k < Cn; k++) acc = fmaf(ft[k], pr[k], acc);
            float d = sqi + g_sq[sB + t] - 2.f * acc;
            sbuf[t] = FLIPU(__float_as_uint(d));
        }
        __syncthreads();
        for (int t = tid; t < Ls; t += 256) {
            unsigned u = sbuf[t];
            int rank = 0;
            for (int j = 0; j < Ls; j++) {
                unsigned uj = sbuf[j];
                rank += (uj < u) || (uj == u && j < t);
            }
            if (rank < KN) {
                nout[rank] = t;
                atomicAdd(&dv[t], 1);
            }
        }
    }
}

// ---------------- kernel 6: exclusive scan of degrees (single block) ----------------
__global__ void scan_kernel() {
    __shared__ int ps[1024];
    int tid = threadIdx.x;
    int start = tid * 25;
    int sum = 0;
    for (int t = start; t < start + 25 && t < NV; t++) sum += g_dvi[t];
    ps[tid] = sum;
    __syncthreads();
    for (int off = 1; off < 1024; off <<= 1) {
        int v = (tid >= off) ? ps[tid - off] : 0;
        __syncthreads();
        ps[tid] += v;
        __syncthreads();
    }
    int excl = (tid == 0) ? 0 : ps[tid - 1];
    for (int t = start; t < start + 25 && t < NV; t++) {
        g_off[t] = excl;
        excl += g_dvi[t];
    }
}

// ---------------- kernel 7: CSR fill (warp per edge) ----------------
__global__ void fill_kernel() {
    int s = blockIdx.y;
    int e = blockIdx.x * 8 + (threadIdx.x >> 5);
    int lane = threadIdx.x & 31;
    int ge = s * Ls + e;
    if (lane < KN) {
        int v  = g_nbr[(size_t)ge * KN + lane];
        int gv = s * Ls + v;
        int pos = atomicAdd(&g_cnt[gv], 1);
        g_adj[g_off[gv] + pos] = ge;
    }
}

// ---------------- kernel 8: theta1 + BN ----------------
__global__ void theta1_kernel(const float* __restrict__ x, const float* __restrict__ w1,
                              const float* __restrict__ b1, const float* __restrict__ g1,
                              const float* __restrict__ be1) {
    __shared__ float ws[Cn * HID];
    int tid = threadIdx.x;
    for (int t = tid; t < Cn * HID; t += 256) ws[t] = w1[t];
    __syncthreads();
    int gv = blockIdx.x * 8 + (tid >> 5);
    int lane = tid & 31;
    const float* f = x + (size_t)gv * Cn;
    float f0 = f[lane], f1 = f[lane + 32];
    float acc = 0.f;
    #pragma unroll
    for (int c = 0; c < 32; c++) acc = fmaf(__shfl_sync(0xffffffffu, f0, c), ws[c * HID + lane], acc);
    #pragma unroll
    for (int c = 0; c < 32; c++) acc = fmaf(__shfl_sync(0xffffffffu, f1, c), ws[(c + 32) * HID + lane], acc);
    g_h1[(size_t)gv * HID + lane] = (acc + b1[lane]) * (g1[lane] * BN_SCALE) + be1[lane];
}

// ---------------- kernel 9: v2e mean, conv1 ----------------
__global__ void v2e1_kernel() {
    int s = blockIdx.y;
    int e = blockIdx.x * 8 + (threadIdx.x >> 5);
    int lane = threadIdx.x & 31;
    int ge = s * Ls + e;
    const int* nb = g_nbr + (size_t)ge * KN;
    int myn = (lane < KN) ? nb[lane] : 0;
    const float* h = g_h1 + (size_t)s * Ls * HID;
    float acc = 0.f;
    #pragma unroll
    for (int j = 0; j < KN; j++) {
        int v = __shfl_sync(0xffffffffu, myn, j);
        acc += h[(size_t)v * HID + lane];
    }
    g_y1[(size_t)ge * HID + lane] = acc * (1.f / KN);
}

// ---------------- kernel 10: e2v mean + relu, conv1 ----------------
__global__ void e2v1_kernel() {
    int gv = blockIdx.x * 8 + (threadIdx.x >> 5);
    int lane = threadIdx.x & 31;
    int cnt = g_dvi[gv];
    int off = g_off[gv];
    float acc = 0.f;
    for (int t = 0; t < cnt; t++) {
        int ge = g_adj[off + t];
        acc += g_y1[(size_t)ge * HID + lane];
    }
    float d = fmaxf((float)cnt, 1.f);
    g_o1[(size_t)gv * HID + lane] = fmaxf(acc / d, 0.f);
}

// ---------------- kernel 11: theta2 + BN ----------------
__global__ void theta2_kernel(const float* __restrict__ w2, const float* __restrict__ b2,
                              const float* __restrict__ g2, const float* __restrict__ be2) {
    __shared__ float ws[HID * Cn];
    int tid = threadIdx.x;
    for (int t = tid; t < HID * Cn; t += 256) ws[t] = w2[t];
    __syncthreads();
    int gv = blockIdx.x * 8 + (tid >> 5);
    int lane = tid & 31;
    float f0 = g_o1[(size_t)gv * HID + lane];
    float a0 = 0.f, a1 = 0.f;
    #pragma unroll
    for (int c = 0; c < 32; c++) {
        float in = __shfl_sync(0xffffffffu, f0, c);
        a0 = fmaf(in, ws[c * Cn + lane], a0);
        a1 = fmaf(in, ws[c * Cn + lane + 32], a1);
    }
    g_h2[(size_t)gv * Cn + lane]      = (a0 + b2[lane])      * (g2[lane]      * BN_SCALE) + be2[lane];
    g_h2[(size_t)gv * Cn + lane + 32] = (a1 + b2[lane + 32]) * (g2[lane + 32] * BN_SCALE) + be2[lane + 32];
}

// ---------------- kernel 12: v2e mean, conv2 ----------------
__global__ void v2e2_kernel() {
    int s = blockIdx.y;
    int e = blockIdx.x * 8 + (threadIdx.x >> 5);
    int lane = threadIdx.x & 31;
    int ge = s * Ls + e;
    const int* nb = g_nbr + (size_t)ge * KN;
    int myn = (lane < KN) ? nb[lane] : 0;
    const float* h = g_h2 + (size_t)s * Ls * Cn;
    float a0 = 0.f, a1 = 0.f;
    #pragma unroll
    for (int j = 0; j < KN; j++) {
        int v = __shfl_sync(0xffffffffu, myn, j);
        const float* hv = h + (size_t)v * Cn;
        a0 += hv[lane];
        a1 += hv[lane + 32];
    }
    g_y2[(size_t)ge * Cn + lane]      = a0 * (1.f / KN);
    g_y2[(size_t)ge * Cn + lane + 32] = a1 * (1.f / KN);
}

// ---------------- kernel 13: e2v mean, conv2 -> output ----------------
__global__ void e2v2_kernel(float* __restrict__ out) {
    int gv = blockIdx.x * 8 + (threadIdx.x >> 5);
    int lane = threadIdx.x & 31;
    int cnt = g_dvi[gv];
    int off = g_off[gv];
    float a0 = 0.f, a1 = 0.f;
    for (int t = 0; t < cnt; t++) {
        int ge = g_adj[off + t];
        const float* y = g_y2 + (size_t)ge * Cn;
        a0 += y[lane];
        a1 += y[lane + 32];
    }
    float d = fmaxf((float)cnt, 1.f);
    out[(size_t)gv * Cn + lane]      = a0 / d;
    out[(size_t)gv * Cn + lane + 32] = a1 / d;
}

// ---------------- launch ----------------
extern "C" void kernel_launch(void* const* d_in, const int* in_sizes, int n_in,
                              void* d_out, int out_size) {
    const float* x   = (const float*)d_in[0];
    const float* w1  = (const float*)d_in[1];
    const float* b1  = (const float*)d_in[2];
    const float* g1  = (const float*)d_in[3];
    const float* be1 = (const float*)d_in[4];
    const float* w2  = (const float*)d_in[5];
    const float* b2  = (const float*)d_in[6];
    const float* g2  = (const float*)d_in[7];
    const float* be2 = (const float*)d_in[8];
    float* out = (float*)d_out;

    sq_kernel<<<NV / 8, 256>>>(x);
    sample_kernel<<<dim3(NS / 64, Ls / 64, Bn), 64>>>(x);
    thr_kernel<<<NV, 256>>>();
    dist_kernel<<<dim3(Ls / 64, Ls / 64, Bn), 64>>>(x);
    select_kernel<<<dim3(Ls, Bn), 256>>>(x);
    scan_kernel<<<1, 1024>>>();
    fill_kernel<<<dim3(Ls / 8, Bn), 256>>>();
    theta1_kernel<<<NV / 8, 256>>>(x, w1, b1, g1, be1);
    v2e1_kernel<<<dim3(Ls / 8, Bn), 256>>>();
    e2v1_kernel<<<NV / 8, 256>>>();
    theta2_kernel<<<NV / 8, 256>>>(w2, b2, g2, be2);
    v2e2_kernel<<<dim3(Ls / 8, Bn), 256>>>();
    e2v2_kernel<<<NV / 8, 256>>>(out);
}

// round 5
// speedup vs baseline: 1.2969x; 1.2969x over previous
#include <cuda_runtime.h>
#include <cfloat>
#include <cstdint>

#define Bn  8
#define Ls  3136      // 56*56
#define Cn  64
#define HID 32
#define KN  30
#define NV  (Bn*Ls)   // 25088 global vertices/edges
#define CAP 2048      // smem candidate capacity per row

// ---------------- device scratch (static globals; no allocations) ----------------
__device__ float    g_sq  [NV];
__device__ float    g_d2  [(size_t)Bn*Ls*Ls];   // 314.7 MB distance matrices
__device__ unsigned g_thr [NV];                 // per-row flipped-key threshold (exact)
__device__ int      g_nbr [(size_t)NV*KN];      // per-edge neighbor lists (sample-local idx)
__device__ int      g_dvi [NV];                 // vertex in-degree (counts)
__device__ int      g_off [NV];                 // CSR offsets
__device__ int      g_cnt [NV];                 // CSR fill cursors
__device__ int      g_adj [(size_t)NV*KN];      // CSR: edges incident to each vertex
__device__ float    g_h1  [(size_t)NV*HID];
__device__ float    g_y1  [(size_t)NV*HID];
__device__ float    g_o1  [(size_t)NV*HID];
__device__ float    g_h2  [(size_t)NV*Cn];
__device__ float    g_y2  [(size_t)NV*Cn];

#define BN_SCALE 0.99999500003749969f
#define FLIPU(u) ((u) ^ ((unsigned)(((int)(u)) >> 31) | 0x80000000u))

// ---------------- kernel 1: row squared norms + zero counters ----------------
__global__ void sq_kernel(const float* __restrict__ x) {
    int tid = threadIdx.x;
    int gv = blockIdx.x * 8 + (tid >> 5);
    int lane = tid & 31;
    const float* p = x + (size_t)gv * Cn;
    float a = p[lane] * p[lane] + p[lane + 32] * p[lane + 32];
    #pragma unroll
    for (int off = 16; off; off >>= 1) a += __shfl_down_sync(0xffffffffu, a, off);
    if (lane == 0) g_sq[gv] = a;
    int t = blockIdx.x * 256 + tid;
    if (t < NV) { g_cnt[t] = 0; g_dvi[t] = 0; }
}

// ---------------- kernel 2: d2 = sq_i + sq_j - 2*(ft @ ft^T), symmetric tiles ----------------
__global__ void __launch_bounds__(64) dist_kernel(const float* __restrict__ x) {
    int ti = blockIdx.y, tj = blockIdx.x;
    if (ti > tj) return;
    int s = blockIdx.z;
    const float* A  = x + (size_t)s * Ls * Cn;
    float*       D  = g_d2 + (size_t)s * Ls * Ls;
    const float* sq = g_sq + s * Ls;
    int i0 = ti << 6, j0 = tj << 6;

    __shared__ __align__(16) float Ast[64][68];
    __shared__ __align__(16) float Bst[64][68];
    int tid = threadIdx.x;   // 64 threads

    for (int f = tid; f < 1024; f += 64) {
        int m = f >> 4, kq = (f & 15) << 2;
        float4 av = *(const float4*)(A + (size_t)(i0 + m) * Cn + kq);
        Ast[kq + 0][m] = av.x; Ast[kq + 1][m] = av.y; Ast[kq + 2][m] = av.z; Ast[kq + 3][m] = av.w;
        float4 bv = *(const float4*)(A + (size_t)(j0 + m) * Cn + kq);
        Bst[kq + 0][m] = bv.x; Bst[kq + 1][m] = bv.y; Bst[kq + 2][m] = bv.z; Bst[kq + 3][m] = bv.w;
    }
    __syncthreads();

    int m0 = (tid >> 3) << 3;
    int n0 = (tid & 7) << 3;
    float acc[8][8];
    #pragma unroll
    for (int r = 0; r < 8; r++)
        #pragma unroll
        for (int c = 0; c < 8; c++) acc[r][c] = 0.f;

    #pragma unroll 8
    for (int k = 0; k < 64; k++) {
        float a[8], b[8];
        *(float4*)(a)     = *(const float4*)&Ast[k][m0];
        *(float4*)(a + 4) = *(const float4*)&Ast[k][m0 + 4];
        *(float4*)(b)     = *(const float4*)&Bst[k][n0];
        *(float4*)(b + 4) = *(const float4*)&Bst[k][n0 + 4];
        #pragma unroll
        for (int r = 0; r < 8; r++)
            #pragma unroll
            for (int c = 0; c < 8; c++) acc[r][c] = fmaf(a[r], b[c], acc[r][c]);
    }

    float sqj[8], sqi[8];
    #pragma unroll
    for (int c = 0; c < 8; c++) sqj[c] = sq[j0 + n0 + c];
    #pragma unroll
    for (int r = 0; r < 8; r++) sqi[r] = sq[i0 + m0 + r];
    #pragma unroll
    for (int r = 0; r < 8; r++)
        #pragma unroll
        for (int c = 0; c < 8; c++) acc[r][c] = sqi[r] + sqj[c] - 2.f * acc[r][c];

    #pragma unroll
    for (int r = 0; r < 8; r++) {
        float* drow = D + (size_t)(i0 + m0 + r) * Ls + j0 + n0;
        *(float4*)(drow)     = make_float4(acc[r][0], acc[r][1], acc[r][2], acc[r][3]);
        *(float4*)(drow + 4) = make_float4(acc[r][4], acc[r][5], acc[r][6], acc[r][7]);
    }
    if (ti != tj) {
        #pragma unroll
        for (int c = 0; c < 8; c++) {
            float* drow = D + (size_t)(j0 + n0 + c) * Ls + i0 + m0;
            *(float4*)(drow)     = make_float4(acc[0][c], acc[1][c], acc[2][c], acc[3][c]);
            *(float4*)(drow + 4) = make_float4(acc[4][c], acc[5][c], acc[6][c], acc[7][c]);
        }
    }
}

// ---------------- kernel 3: per-row threshold = exact 30th smallest of 256 stored samples ----
__global__ void __launch_bounds__(256) thr_kernel() {
    int gv = blockIdx.x;
    const float* row = g_d2 + (size_t)gv * Ls;
    __shared__ unsigned us[256];
    int tid = threadIdx.x;
    unsigned u = FLIPU(__float_as_uint(row[tid * 12]));   // stride-12 subset (decorrelated)
    us[tid] = u;
    __syncthreads();
    int rank = 0;
    #pragma unroll 8
    for (int j = 0; j < 256; j++) {
        unsigned uj = us[j];
        rank += (uj < u) || (uj == u && j < tid);
    }
    if (rank == KN - 1) g_thr[gv] = u;   // exact key: stored values, no margin needed
}

// ---------------- kernel 4: stream-filter row by threshold + bitonic select top-30 -----
__global__ void __launch_bounds__(256) filtersel_kernel() {
    int s = blockIdx.y, i = blockIdx.x;
    int sB = s * Ls;
    int gv = sB + i;
    const uint4* row4 = (const uint4*)(g_d2 + (size_t)gv * Ls);
    __shared__ __align__(16) unsigned long long cand[CAP];   // 16 KB
    __shared__ int scnt;
    int tid = threadIdx.x;   // 256
    if (tid == 0) scnt = 0;
    __syncthreads();

    unsigned T = g_thr[gv];

    // streaming filter: 784 uint4 = 3136 keys, coalesced
    #define FPROC(vv, base) {                                                     \
        unsigned a = FLIPU(vv.x), b = FLIPU(vv.y), c = FLIPU(vv.z), d = FLIPU(vv.w); \
        if (a <= T) { int p = atomicAdd(&scnt, 1); if (p < CAP) cand[p] = ((unsigned long long)a << 32) | (unsigned)((base));     }  \
        if (b <= T) { int p = atomicAdd(&scnt, 1); if (p < CAP) cand[p] = ((unsigned long long)b << 32) | (unsigned)((base) + 1); }  \
        if (c <= T) { int p = atomicAdd(&scnt, 1); if (p < CAP) cand[p] = ((unsigned long long)c << 32) | (unsigned)((base) + 2); }  \
        if (d <= T) { int p = atomicAdd(&scnt, 1); if (p < CAP) cand[p] = ((unsigned long long)d << 32) | (unsigned)((base) + 3); }  \
    }
    {
        uint4 v0 = row4[tid];
        uint4 v1 = row4[tid + 256];
        uint4 v2 = row4[tid + 512];
        FPROC(v0, tid * 4);
        FPROC(v1, (tid + 256) * 4);
        FPROC(v2, (tid + 512) * 4);
        if (tid < 784 - 768) {
            uint4 v3 = row4[tid + 768];
            FPROC(v3, (tid + 768) * 4);
        }
    }
    #undef FPROC
    __syncthreads();

    int cnt = scnt;
    int* nout = g_nbr + (size_t)gv * KN;
    int* dv = g_dvi + sB;

    if (cnt <= CAP) {
        // pad to power of two and bitonic sort ascending by (key, idx)
        int n = 512;
        while (n < cnt) n <<= 1;
        for (int t = cnt + tid; t < n; t += 256) cand[t] = ~0ull;
        __syncthreads();
        for (int k = 2; k <= n; k <<= 1) {
            for (int j = k >> 1; j > 0; j >>= 1) {
                for (int idx = tid; idx < n; idx += 256) {
                    int ixj = idx ^ j;
                    if (ixj > idx) {
                        unsigned long long a = cand[idx], b = cand[ixj];
                        bool up = ((idx & k) == 0);
                        if (up ? (a > b) : (a < b)) { cand[idx] = b; cand[ixj] = a; }
                    }
                }
                __syncthreads();
            }
        }
        if (tid < KN) {
            int idx = (int)(cand[tid] & 0xffffffffull);
            nout[tid] = idx;
            atomicAdd(&dv[idx], 1);
        }
    } else {
        // never-expected exact fallback: full-row rank select (reuse cand as u32 stage)
        unsigned* su = (unsigned*)cand;   // 3136 u32 = 12.5 KB <= 16 KB
        const unsigned* rowu = (const unsigned*)(g_d2 + (size_t)gv * Ls);
        for (int t = tid; t < Ls; t += 256) su[t] = FLIPU(rowu[t]);
        __syncthreads();
        for (int t = tid; t < Ls; t += 256) {
            unsigned u = su[t];
            int rank = 0;
            for (int j = 0; j < Ls; j++) {
                unsigned uj = su[j];
                rank += (uj < u) || (uj == u && j < t);
            }
            if (rank < KN) {
                nout[rank] = t;
                atomicAdd(&dv[t], 1);
            }
        }
    }
}

// ---------------- kernel 5: exclusive scan of degrees (single block) ----------------
__global__ void scan_kernel() {
    __shared__ int ps[1024];
    int tid = threadIdx.x;
    int start = tid * 25;
    int sum = 0;
    for (int t = start; t < start + 25 && t < NV; t++) sum += g_dvi[t];
    ps[tid] = sum;
    __syncthreads();
    for (int off = 1; off < 1024; off <<= 1) {
        int v = (tid >= off) ? ps[tid - off] : 0;
        __syncthreads();
        ps[tid] += v;
        __syncthreads();
    }
    int excl = (tid == 0) ? 0 : ps[tid - 1];
    for (int t = start; t < start + 25 && t < NV; t++) {
        g_off[t] = excl;
        excl += g_dvi[t];
    }
}

// ---------------- kernel 6: CSR fill (warp per edge) ----------------
__global__ void fill_kernel() {
    int s = blockIdx.y;
    int e = blockIdx.x * 8 + (threadIdx.x >> 5);
    int lane = threadIdx.x & 31;
    int ge = s * Ls + e;
    if (lane < KN) {
        int v  = g_nbr[(size_t)ge * KN + lane];
        int gv = s * Ls + v;
        int pos = atomicAdd(&g_cnt[gv], 1);
        g_adj[g_off[gv] + pos] = ge;
    }
}

// ---------------- kernel 7: theta1 + BN ----------------
__global__ void theta1_kernel(const float* __restrict__ x, const float* __restrict__ w1,
                              const float* __restrict__ b1, const float* __restrict__ g1,
                              const float* __restrict__ be1) {
    __shared__ float ws[Cn * HID];
    int tid = threadIdx.x;
    for (int t = tid; t < Cn * HID; t += 256) ws[t] = w1[t];
    __syncthreads();
    int gv = blockIdx.x * 8 + (tid >> 5);
    int lane = tid & 31;
    const float* f = x + (size_t)gv * Cn;
    float f0 = f[lane], f1 = f[lane + 32];
    float acc = 0.f;
    #pragma unroll
    for (int c = 0; c < 32; c++) acc = fmaf(__shfl_sync(0xffffffffu, f0, c), ws[c * HID + lane], acc);
    #pragma unroll
    for (int c = 0; c < 32; c++) acc = fmaf(__shfl_sync(0xffffffffu, f1, c), ws[(c + 32) * HID + lane], acc);
    g_h1[(size_t)gv * HID + lane] = (acc + b1[lane]) * (g1[lane] * BN_SCALE) + be1[lane];
}

// ---------------- kernel 8: v2e mean, conv1 ----------------
__global__ void v2e1_kernel() {
    int s = blockIdx.y;
    int e = blockIdx.x * 8 + (threadIdx.x >> 5);
    int lane = threadIdx.x & 31;
    int ge = s * Ls + e;
    const int* nb = g_nbr + (size_t)ge * KN;
    int myn = (lane < KN) ? nb[lane] : 0;
    const float* h = g_h1 + (size_t)s * Ls * HID;
    float acc = 0.f;
    #pragma unroll
    for (int j = 0; j < KN; j++) {
        int v = __shfl_sync(0xffffffffu, myn, j);
        acc += h[(size_t)v * HID + lane];
    }
    g_y1[(size_t)ge * HID + lane] = acc * (1.f / KN);
}

// ---------------- kernel 9: e2v mean + relu, conv1 ----------------
__global__ void e2v1_kernel() {
    int gv = blockIdx.x * 8 + (threadIdx.x >> 5);
    int lane = threadIdx.x & 31;
    int cnt = g_dvi[gv];
    int off = g_off[gv];
    float acc = 0.f;
    for (int t = 0; t < cnt; t++) {
        int ge = g_adj[off + t];
        acc += g_y1[(size_t)ge * HID + lane];
    }
    float d = fmaxf((float)cnt, 1.f);
    g_o1[(size_t)gv * HID + lane] = fmaxf(acc / d, 0.f);
}

// ---------------- kernel 10: theta2 + BN ----------------
__global__ void theta2_kernel(const float* __restrict__ w2, const float* __restrict__ b2,
                              const float* __restrict__ g2, const float* __restrict__ be2) {
    __shared__ float ws[HID * Cn];
    int tid = threadIdx.x;
    for (int t = tid; t < HID * Cn; t += 256) ws[t] = w2[t];
    __syncthreads();
    int gv = blockIdx.x * 8 + (tid >> 5);
    int lane = tid & 31;
    float f0 = g_o1[(size_t)gv * HID + lane];
    float a0 = 0.f, a1 = 0.f;
    #pragma unroll
    for (int c = 0; c < 32; c++) {
        float in = __shfl_sync(0xffffffffu, f0, c);
        a0 = fmaf(in, ws[c * Cn + lane], a0);
        a1 = fmaf(in, ws[c * Cn + lane + 32], a1);
    }
    g_h2[(size_t)gv * Cn + lane]      = (a0 + b2[lane])      * (g2[lane]      * BN_SCALE) + be2[lane];
    g_h2[(size_t)gv * Cn + lane + 32] = (a1 + b2[lane + 32]) * (g2[lane + 32] * BN_SCALE) + be2[lane + 32];
}

// ---------------- kernel 11: v2e mean, conv2 ----------------
__global__ void v2e2_kernel() {
    int s = blockIdx.y;
    int e = blockIdx.x * 8 + (threadIdx.x >> 5);
    int lane = threadIdx.x & 31;
    int ge = s * Ls + e;
    const int* nb = g_nbr + (size_t)ge * KN;
    int myn = (lane < KN) ? nb[lane] : 0;
    const float* h = g_h2 + (size_t)s * Ls * Cn;
    float a0 = 0.f, a1 = 0.f;
    #pragma unroll
    for (int j = 0; j < KN; j++) {
        int v = __shfl_sync(0xffffffffu, myn, j);
        const float* hv = h + (size_t)v * Cn;
        a0 += hv[lane];
        a1 += hv[lane + 32];
    }
    g_y2[(size_t)ge * Cn + lane]      = a0 * (1.f / KN);
    g_y2[(size_t)ge * Cn + lane + 32] = a1 * (1.f / KN);
}

// ---------------- kernel 12: e2v mean, conv2 -> output ----------------
__global__ void e2v2_kernel(float* __restrict__ out) {
    int gv = blockIdx.x * 8 + (threadIdx.x >> 5);
    int lane = threadIdx.x & 31;
    int cnt = g_dvi[gv];
    int off = g_off[gv];
    float a0 = 0.f, a1 = 0.f;
    for (int t = 0; t < cnt; t++) {
        int ge = g_adj[off + t];
        const float* y = g_y2 + (size_t)ge * Cn;
        a0 += y[lane];
        a1 += y[lane + 32];
    }
    float d = fmaxf((float)cnt, 1.f);
    out[(size_t)gv * Cn + lane]      = a0 / d;
    out[(size_t)gv * Cn + lane + 32] = a1 / d;
}

// ---------------- launch ----------------
extern "C" void kernel_launch(void* const* d_in, const int* in_sizes, int n_in,
                              void* d_out, int out_size) {
    const float* x   = (const float*)d_in[0];
    const float* w1  = (const float*)d_in[1];
    const float* b1  = (const float*)d_in[2];
    const float* g1  = (const float*)d_in[3];
    const float* be1 = (const float*)d_in[4];
    const float* w2  = (const float*)d_in[5];
    const float* b2  = (const float*)d_in[6];
    const float* g2  = (const float*)d_in[7];
    const float* be2 = (const float*)d_in[8];
    float* out = (float*)d_out;

    sq_kernel<<<NV / 8, 256>>>(x);
    dist_kernel<<<dim3(Ls / 64, Ls / 64, Bn), 64>>>(x);
    thr_kernel<<<NV, 256>>>();
    filtersel_kernel<<<dim3(Ls, Bn), 256>>>();
    scan_kernel<<<1, 1024>>>();
    fill_kernel<<<dim3(Ls / 8, Bn), 256>>>();
    theta1_kernel<<<NV / 8, 256>>>(x, w1, b1, g1, be1);
    v2e1_kernel<<<dim3(Ls / 8, Bn), 256>>>();
    e2v1_kernel<<<NV / 8, 256>>>();
    theta2_kernel<<<NV / 8, 256>>>(w2, b2, g2, be2);
    v2e2_kernel<<<dim3(Ls / 8, Bn), 256>>>();
    e2v2_kernel<<<NV / 8, 256>>>(out);
}

// round 6
// speedup vs baseline: 1.9062x; 1.4699x over previous
#include <cuda_runtime.h>
#include <cfloat>
#include <cstdint>

#define Bn  8
#define Ls  3136      // 56*56
#define Cn  64
#define HID 32
#define KN  30
#define NV  (Bn*Ls)   // 25088 global vertices/edges
#define CAP 512       // candidate capacity (expected ~150)
#define RSEL 12       // threshold = RSEL-th smallest of 256 samples

// ---------------- device scratch (static globals; no allocations) ----------------
__device__ float    g_sq  [NV];
__device__ float    g_d2  [(size_t)Bn*Ls*Ls];   // 314.7 MB distance matrices
__device__ int      g_nbr [(size_t)NV*KN];      // per-edge neighbor lists (sample-local idx)
__device__ int      g_dvi [NV];                 // vertex in-degree (counts)
__device__ int      g_off [NV];                 // CSR offsets
__device__ int      g_cnt [NV];                 // CSR fill cursors
__device__ int      g_adj [(size_t)NV*KN];      // CSR: edges incident to each vertex
__device__ float    g_h1  [(size_t)NV*HID];
__device__ float    g_y1  [(size_t)NV*HID];
__device__ float    g_o1  [(size_t)NV*HID];
__device__ float    g_h2  [(size_t)NV*Cn];
__device__ float    g_y2  [(size_t)NV*Cn];

#define BN_SCALE 0.99999500003749969f
#define FLIPU(u) ((u) ^ ((unsigned)(((int)(u)) >> 31) | 0x80000000u))

// ---------------- kernel 1: row squared norms + zero counters ----------------
__global__ void sq_kernel(const float* __restrict__ x) {
    int tid = threadIdx.x;
    int gv = blockIdx.x * 8 + (tid >> 5);
    int lane = tid & 31;
    const float* p = x + (size_t)gv * Cn;
    float a = p[lane] * p[lane] + p[lane + 32] * p[lane + 32];
    #pragma unroll
    for (int off = 16; off; off >>= 1) a += __shfl_down_sync(0xffffffffu, a, off);
    if (lane == 0) g_sq[gv] = a;
    int t = blockIdx.x * 256 + tid;
    if (t < NV) { g_cnt[t] = 0; g_dvi[t] = 0; }
}

// ---------------- kernel 2: d2 = sq_i + sq_j - 2*(ft @ ft^T), symmetric tiles ----------------
__global__ void __launch_bounds__(64) dist_kernel(const float* __restrict__ x) {
    int ti = blockIdx.y, tj = blockIdx.x;
    if (ti > tj) return;
    int s = blockIdx.z;
    const float* A  = x + (size_t)s * Ls * Cn;
    float*       D  = g_d2 + (size_t)s * Ls * Ls;
    const float* sq = g_sq + s * Ls;
    int i0 = ti << 6, j0 = tj << 6;

    __shared__ __align__(16) float Ast[64][68];
    __shared__ __align__(16) float Bst[64][68];
    int tid = threadIdx.x;   // 64 threads

    for (int f = tid; f < 1024; f += 64) {
        int m = f >> 4, kq = (f & 15) << 2;
        float4 av = *(const float4*)(A + (size_t)(i0 + m) * Cn + kq);
        Ast[kq + 0][m] = av.x; Ast[kq + 1][m] = av.y; Ast[kq + 2][m] = av.z; Ast[kq + 3][m] = av.w;
        float4 bv = *(const float4*)(A + (size_t)(j0 + m) * Cn + kq);
        Bst[kq + 0][m] = bv.x; Bst[kq + 1][m] = bv.y; Bst[kq + 2][m] = bv.z; Bst[kq + 3][m] = bv.w;
    }
    __syncthreads();

    int m0 = (tid >> 3) << 3;
    int n0 = (tid & 7) << 3;
    float acc[8][8];
    #pragma unroll
    for (int r = 0; r < 8; r++)
        #pragma unroll
        for (int c = 0; c < 8; c++) acc[r][c] = 0.f;

    #pragma unroll 8
    for (int k = 0; k < 64; k++) {
        float a[8], b[8];
        *(float4*)(a)     = *(const float4*)&Ast[k][m0];
        *(float4*)(a + 4) = *(const float4*)&Ast[k][m0 + 4];
        *(float4*)(b)     = *(const float4*)&Bst[k][n0];
        *(float4*)(b + 4) = *(const float4*)&Bst[k][n0 + 4];
        #pragma unroll
        for (int r = 0; r < 8; r++)
            #pragma unroll
            for (int c = 0; c < 8; c++) acc[r][c] = fmaf(a[r], b[c], acc[r][c]);
    }

    float sqj[8], sqi[8];
    #pragma unroll
    for (int c = 0; c < 8; c++) sqj[c] = sq[j0 + n0 + c];
    #pragma unroll
    for (int r = 0; r < 8; r++) sqi[r] = sq[i0 + m0 + r];
    #pragma unroll
    for (int r = 0; r < 8; r++)
        #pragma unroll
        for (int c = 0; c < 8; c++) acc[r][c] = sqi[r] + sqj[c] - 2.f * acc[r][c];

    #pragma unroll
    for (int r = 0; r < 8; r++) {
        float* drow = D + (size_t)(i0 + m0 + r) * Ls + j0 + n0;
        *(float4*)(drow)     = make_float4(acc[r][0], acc[r][1], acc[r][2], acc[r][3]);
        *(float4*)(drow + 4) = make_float4(acc[r][4], acc[r][5], acc[r][6], acc[r][7]);
    }
    if (ti != tj) {
        #pragma unroll
        for (int c = 0; c < 8; c++) {
            float* drow = D + (size_t)(j0 + n0 + c) * Ls + i0 + m0;
            *(float4*)(drow)     = make_float4(acc[0][c], acc[1][c], acc[2][c], acc[3][c]);
            *(float4*)(drow + 4) = make_float4(acc[4][c], acc[5][c], acc[6][c], acc[7][c]);
        }
    }
}

// ---------------- kernel 3: fused threshold + filter + exact top-30 select ----------
__global__ void __launch_bounds__(256) select_kernel() {
    int s = blockIdx.y, i = blockIdx.x;
    int sB = s * Ls;
    int gv = sB + i;
    const float* row = g_d2 + (size_t)gv * Ls;
    const uint4* row4 = (const uint4*)row;

    __shared__ __align__(16) unsigned sbuf[Ls];     // 12.5 KB (fallback keys / candidate overlay)
    __shared__ unsigned samp[256];
    __shared__ unsigned sT;
    __shared__ int scnt;
    unsigned long long* cand = (unsigned long long*)sbuf;  // 1568 u64 slots, use CAP=512

    int tid = threadIdx.x;   // 256
    if (tid == 0) scnt = 0;

    // load entire row into registers (flipped), coalesced
    uint4 v0 = row4[tid];
    uint4 v1 = row4[tid + 256];
    uint4 v2 = row4[tid + 512];
    uint4 v3 = make_uint4(0xffffffffu, 0xffffffffu, 0xffffffffu, 0xffffffffu);
    bool rem = (tid < 784 - 768);
    if (rem) v3 = row4[tid + 768];
    #define FL4(v) { v.x = FLIPU(v.x); v.y = FLIPU(v.y); v.z = FLIPU(v.z); v.w = FLIPU(v.w); }
    FL4(v0) FL4(v1) FL4(v2) FL4(v3)
    #undef FL4

    // per-row threshold: RSEL-th smallest of 256 stride-12 samples (L2-hot)
    unsigned u = FLIPU(__float_as_uint(row[tid * 12]));
    samp[tid] = u;
    __syncthreads();
    int rank = 0;
    #pragma unroll 8
    for (int j = 0; j < 256; j++) {
        unsigned uj = samp[j];
        rank += (uj < u) || (uj == u && j < tid);
    }
    if (rank == RSEL - 1) sT = u;
    __syncthreads();
    unsigned T = sT;

    // filter registers -> candidates
    #define FPROC(vv, base) {                                                                  \
        if (vv.x <= T) { int p = atomicAdd(&scnt, 1); if (p < CAP) cand[p] = ((unsigned long long)vv.x << 32) | (unsigned)((base));     } \
        if (vv.y <= T) { int p = atomicAdd(&scnt, 1); if (p < CAP) cand[p] = ((unsigned long long)vv.y << 32) | (unsigned)((base) + 1); } \
        if (vv.z <= T) { int p = atomicAdd(&scnt, 1); if (p < CAP) cand[p] = ((unsigned long long)vv.z << 32) | (unsigned)((base) + 2); } \
        if (vv.w <= T) { int p = atomicAdd(&scnt, 1); if (p < CAP) cand[p] = ((unsigned long long)vv.w << 32) | (unsigned)((base) + 3); } \
    }
    FPROC(v0, tid * 4)
    FPROC(v1, (tid + 256) * 4)
    FPROC(v2, (tid + 512) * 4)
    if (rem) FPROC(v3, (tid + 768) * 4)
    #undef FPROC
    __syncthreads();

    int cnt = scnt;
    int* nout = g_nbr + (size_t)gv * KN;
    int* dv = g_dvi + sB;

    if (cnt >= KN && cnt <= CAP) {
        // exact rank-select among candidates (u64 packs key then idx -> reference tie order)
        for (int t = tid; t < cnt; t += 256) {
            unsigned long long K = cand[t];
            int r = 0;
            for (int j = 0; j < cnt; j++) r += (cand[j] < K);
            if (r < KN) {
                int idx = (int)(K & 0xffffffffull);
                nout[r] = idx;
                atomicAdd(&dv[idx], 1);
            }
        }
    } else {
        // rare exact fallback (~0.1% of rows): full-row rank select from registers
        __syncthreads();                 // cand overlay dead; safe to overwrite
        *(uint4*)&sbuf[tid * 4]         = v0;
        *(uint4*)&sbuf[(tid + 256) * 4] = v1;
        *(uint4*)&sbuf[(tid + 512) * 4] = v2;
        if (rem) *(uint4*)&sbuf[(tid + 768) * 4] = v3;
        __syncthreads();
        for (int t = tid; t < Ls; t += 256) {
            unsigned ut = sbuf[t];
            int r = 0;
            for (int j = 0; j < Ls; j++) {
                unsigned uj = sbuf[j];
                r += (uj < ut) || (uj == ut && j < t);
            }
            if (r < KN) {
                nout[r] = t;
                atomicAdd(&dv[t], 1);
            }
        }
    }
}

// ---------------- kernel 4: exclusive scan of degrees (single block) ----------------
__global__ void scan_kernel() {
    __shared__ int ps[1024];
    int tid = threadIdx.x;
    int start = tid * 25;
    int sum = 0;
    for (int t = start; t < start + 25 && t < NV; t++) sum += g_dvi[t];
    ps[tid] = sum;
    __syncthreads();
    for (int off = 1; off < 1024; off <<= 1) {
        int v = (tid >= off) ? ps[tid - off] : 0;
        __syncthreads();
        ps[tid] += v;
        __syncthreads();
    }
    int excl = (tid == 0) ? 0 : ps[tid - 1];
    for (int t = start; t < start + 25 && t < NV; t++) {
        g_off[t] = excl;
        excl += g_dvi[t];
    }
}

// ---------------- kernel 5: CSR fill (warp per edge) ----------------
__global__ void fill_kernel() {
    int s = blockIdx.y;
    int e = blockIdx.x * 8 + (threadIdx.x >> 5);
    int lane = threadIdx.x & 31;
    int ge = s * Ls + e;
    if (lane < KN) {
        int v  = g_nbr[(size_t)ge * KN + lane];
        int gv = s * Ls + v;
        int pos = atomicAdd(&g_cnt[gv], 1);
        g_adj[g_off[gv] + pos] = ge;
    }
}

// ---------------- kernel 6: theta1 + BN ----------------
__global__ void theta1_kernel(const float* __restrict__ x, const float* __restrict__ w1,
                              const float* __restrict__ b1, const float* __restrict__ g1,
                              const float* __restrict__ be1) {
    __shared__ float ws[Cn * HID];
    int tid = threadIdx.x;
    for (int t = tid; t < Cn * HID; t += 256) ws[t] = w1[t];
    __syncthreads();
    int gv = blockIdx.x * 8 + (tid >> 5);
    int lane = tid & 31;
    const float* f = x + (size_t)gv * Cn;
    float f0 = f[lane], f1 = f[lane + 32];
    float acc = 0.f;
    #pragma unroll
    for (int c = 0; c < 32; c++) acc = fmaf(__shfl_sync(0xffffffffu, f0, c), ws[c * HID + lane], acc);
    #pragma unroll
    for (int c = 0; c < 32; c++) acc = fmaf(__shfl_sync(0xffffffffu, f1, c), ws[(c + 32) * HID + lane], acc);
    g_h1[(size_t)gv * HID + lane] = (acc + b1[lane]) * (g1[lane] * BN_SCALE) + be1[lane];
}

// ---------------- kernel 7: v2e mean, conv1 ----------------
__global__ void v2e1_kernel() {
    int s = blockIdx.y;
    int e = blockIdx.x * 8 + (threadIdx.x >> 5);
    int lane = threadIdx.x & 31;
    int ge = s * Ls + e;
    const int* nb = g_nbr + (size_t)ge * KN;
    int myn = (lane < KN) ? nb[lane] : 0;
    const float* h = g_h1 + (size_t)s * Ls * HID;
    float acc = 0.f;
    #pragma unroll
    for (int j = 0; j < KN; j++) {
        int v = __shfl_sync(0xffffffffu, myn, j);
        acc += h[(size_t)v * HID + lane];
    }
    g_y1[(size_t)ge * HID + lane] = acc * (1.f / KN);
}

// ---------------- kernel 8: e2v mean + relu, conv1 ----------------
__global__ void e2v1_kernel() {
    int gv = blockIdx.x * 8 + (threadIdx.x >> 5);
    int lane = threadIdx.x & 31;
    int cnt = g_dvi[gv];
    int off = g_off[gv];
    float acc = 0.f;
    for (int t = 0; t < cnt; t++) {
        int ge = g_adj[off + t];
        acc += g_y1[(size_t)ge * HID + lane];
    }
    float d = fmaxf((float)cnt, 1.f);
    g_o1[(size_t)gv * HID + lane] = fmaxf(acc / d, 0.f);
}

// ---------------- kernel 9: theta2 + BN ----------------
__global__ void theta2_kernel(const float* __restrict__ w2, const float* __restrict__ b2,
                              const float* __restrict__ g2, const float* __restrict__ be2) {
    __shared__ float ws[HID * Cn];
    int tid = threadIdx.x;
    for (int t = tid; t < HID * Cn; t += 256) ws[t] = w2[t];
    __syncthreads();
    int gv = blockIdx.x * 8 + (tid >> 5);
    int lane = tid & 31;
    float f0 = g_o1[(size_t)gv * HID + lane];
    float a0 = 0.f, a1 = 0.f;
    #pragma unroll
    for (int c = 0; c < 32; c++) {
        float in = __shfl_sync(0xffffffffu, f0, c);
        a0 = fmaf(in, ws[c * Cn + lane], a0);
        a1 = fmaf(in, ws[c * Cn + lane + 32], a1);
    }
    g_h2[(size_t)gv * Cn + lane]      = (a0 + b2[lane])      * (g2[lane]      * BN_SCALE) + be2[lane];
    g_h2[(size_t)gv * Cn + lane + 32] = (a1 + b2[lane + 32]) * (g2[lane + 32] * BN_SCALE) + be2[lane + 32];
}

// ---------------- kernel 10: v2e mean, conv2 ----------------
__global__ void v2e2_kernel() {
    int s = blockIdx.y;
    int e = blockIdx.x * 8 + (threadIdx.x >> 5);
    int lane = threadIdx.x & 31;
    int ge = s * Ls + e;
    const int* nb = g_nbr + (size_t)ge * KN;
    int myn = (lane < KN) ? nb[lane] : 0;
    const float* h = g_h2 + (size_t)s * Ls * Cn;
    float a0 = 0.f, a1 = 0.f;
    #pragma unroll
    for (int j = 0; j < KN; j++) {
        int v = __shfl_sync(0xffffffffu, myn, j);
        const float* hv = h + (size_t)v * Cn;
        a0 += hv[lane];
        a1 += hv[lane + 32];
    }
    g_y2[(size_t)ge * Cn + lane]      = a0 * (1.f / KN);
    g_y2[(size_t)ge * Cn + lane + 32] = a1 * (1.f / KN);
}

// ---------------- kernel 11: e2v mean, conv2 -> output ----------------
__global__ void e2v2_kernel(float* __restrict__ out) {
    int gv = blockIdx.x * 8 + (threadIdx.x >> 5);
    int lane = threadIdx.x & 31;
    int cnt = g_dvi[gv];
    int off = g_off[gv];
    float a0 = 0.f, a1 = 0.f;
    for (int t = 0; t < cnt; t++) {
        int ge = g_adj[off + t];
        const float* y = g_y2 + (size_t)ge * Cn;
        a0 += y[lane];
        a1 += y[lane + 32];
    }
    float d = fmaxf((float)cnt, 1.f);
    out[(size_t)gv * Cn + lane]      = a0 / d;
    out[(size_t)gv * Cn + lane + 32] = a1 / d;
}

// ---------------- launch ----------------
extern "C" void kernel_launch(void* const* d_in, const int* in_sizes, int n_in,
                              void* d_out, int out_size) {
    const float* x   = (const float*)d_in[0];
    const float* w1  = (const float*)d_in[1];
    const float* b1  = (const float*)d_in[2];
    const float* g1  = (const float*)d_in[3];
    const float* be1 = (const float*)d_in[4];
    const float* w2  = (const float*)d_in[5];
    const float* b2  = (const float*)d_in[6];
    const float* g2  = (const float*)d_in[7];
    const float* be2 = (const float*)d_in[8];
    float* out = (float*)d_out;

    sq_kernel<<<NV / 8, 256>>>(x);
    dist_kernel<<<dim3(Ls / 64, Ls / 64, Bn), 64>>>(x);
    select_kernel<<<dim3(Ls, Bn), 256>>>();
    scan_kernel<<<1, 1024>>>();
    fill_kernel<<<dim3(Ls / 8, Bn), 256>>>();
    theta1_kernel<<<NV / 8, 256>>>(x, w1, b1, g1, be1);
    v2e1_kernel<<<dim3(Ls / 8, Bn), 256>>>();
    e2v1_kernel<<<NV / 8, 256>>>();
    theta2_kernel<<<NV / 8, 256>>>(w2, b2, g2, be2);
    v2e2_kernel<<<dim3(Ls / 8, Bn), 256>>>();
    e2v2_kernel<<<NV / 8, 256>>>(out);
}

// round 7
// speedup vs baseline: 2.0603x; 1.0808x over previous
#include <cuda_runtime.h>
#include <cfloat>
#include <cstdint>

#define Bn  8
#define Ls  3136      // 56*56
#define Cn  64
#define HID 32
#define KN  30
#define NV  (Bn*Ls)   // 25088 global vertices/edges
#define CAP 1536      // candidate capacity (sbuf holds 1568 u64)

// ---------------- device scratch (static globals; no allocations) ----------------
__device__ float    g_sq  [NV];
__device__ float    g_d2  [(size_t)Bn*Ls*Ls];   // 314.7 MB distance matrices
__device__ int      g_nbr [(size_t)NV*KN];      // per-edge neighbor lists (sample-local idx)
__device__ int      g_dvi [NV];                 // vertex in-degree (counts)
__device__ int      g_off [NV];                 // CSR offsets
__device__ int      g_cnt [NV];                 // CSR fill cursors
__device__ int      g_adj [(size_t)NV*KN];      // CSR: edges incident to each vertex
__device__ float    g_h1  [(size_t)NV*HID];
__device__ float    g_y1  [(size_t)NV*HID];
__device__ float    g_o1  [(size_t)NV*HID];
__device__ float    g_h2  [(size_t)NV*Cn];
__device__ float    g_y2  [(size_t)NV*Cn];

#define BN_SCALE 0.99999500003749969f
#define FLIPU(u) ((u) ^ ((unsigned)(((int)(u)) >> 31) | 0x80000000u))

// ---------------- kernel 1: row squared norms + zero counters ----------------
__global__ void sq_kernel(const float* __restrict__ x) {
    int tid = threadIdx.x;
    int gv = blockIdx.x * 8 + (tid >> 5);
    int lane = tid & 31;
    const float* p = x + (size_t)gv * Cn;
    float a = p[lane] * p[lane] + p[lane + 32] * p[lane + 32];
    #pragma unroll
    for (int off = 16; off; off >>= 1) a += __shfl_down_sync(0xffffffffu, a, off);
    if (lane == 0) g_sq[gv] = a;
    int t = blockIdx.x * 256 + tid;
    if (t < NV) { g_cnt[t] = 0; g_dvi[t] = 0; }
}

// ---------------- kernel 2: d2 = sq_i + sq_j - 2*(ft @ ft^T), symmetric tiles ----------------
__global__ void __launch_bounds__(64) dist_kernel(const float* __restrict__ x) {
    int ti = blockIdx.y, tj = blockIdx.x;
    if (ti > tj) return;
    int s = blockIdx.z;
    const float* A  = x + (size_t)s * Ls * Cn;
    float*       D  = g_d2 + (size_t)s * Ls * Ls;
    const float* sq = g_sq + s * Ls;
    int i0 = ti << 6, j0 = tj << 6;

    __shared__ __align__(16) float Ast[64][68];
    __shared__ __align__(16) float Bst[64][68];
    int tid = threadIdx.x;   // 64 threads

    for (int f = tid; f < 1024; f += 64) {
        int m = f >> 4, kq = (f & 15) << 2;
        float4 av = *(const float4*)(A + (size_t)(i0 + m) * Cn + kq);
        Ast[kq + 0][m] = av.x; Ast[kq + 1][m] = av.y; Ast[kq + 2][m] = av.z; Ast[kq + 3][m] = av.w;
        float4 bv = *(const float4*)(A + (size_t)(j0 + m) * Cn + kq);
        Bst[kq + 0][m] = bv.x; Bst[kq + 1][m] = bv.y; Bst[kq + 2][m] = bv.z; Bst[kq + 3][m] = bv.w;
    }
    __syncthreads();

    int m0 = (tid >> 3) << 3;
    int n0 = (tid & 7) << 3;
    float acc[8][8];
    #pragma unroll
    for (int r = 0; r < 8; r++)
        #pragma unroll
        for (int c = 0; c < 8; c++) acc[r][c] = 0.f;

    #pragma unroll 8
    for (int k = 0; k < 64; k++) {
        float a[8], b[8];
        *(float4*)(a)     = *(const float4*)&Ast[k][m0];
        *(float4*)(a + 4) = *(const float4*)&Ast[k][m0 + 4];
        *(float4*)(b)     = *(const float4*)&Bst[k][n0];
        *(float4*)(b + 4) = *(const float4*)&Bst[k][n0 + 4];
        #pragma unroll
        for (int r = 0; r < 8; r++)
            #pragma unroll
            for (int c = 0; c < 8; c++) acc[r][c] = fmaf(a[r], b[c], acc[r][c]);
    }

    float sqj[8], sqi[8];
    #pragma unroll
    for (int c = 0; c < 8; c++) sqj[c] = sq[j0 + n0 + c];
    #pragma unroll
    for (int r = 0; r < 8; r++) sqi[r] = sq[i0 + m0 + r];
    #pragma unroll
    for (int r = 0; r < 8; r++)
        #pragma unroll
        for (int c = 0; c < 8; c++) acc[r][c] = sqi[r] + sqj[c] - 2.f * acc[r][c];

    #pragma unroll
    for (int r = 0; r < 8; r++) {
        float* drow = D + (size_t)(i0 + m0 + r) * Ls + j0 + n0;
        *(float4*)(drow)     = make_float4(acc[r][0], acc[r][1], acc[r][2], acc[r][3]);
        *(float4*)(drow + 4) = make_float4(acc[r][4], acc[r][5], acc[r][6], acc[r][7]);
    }
    if (ti != tj) {
        #pragma unroll
        for (int c = 0; c < 8; c++) {
            float* drow = D + (size_t)(j0 + n0 + c) * Ls + i0 + m0;
            *(float4*)(drow)     = make_float4(acc[0][c], acc[1][c], acc[2][c], acc[3][c]);
            *(float4*)(drow + 4) = make_float4(acc[4][c], acc[5][c], acc[6][c], acc[7][c]);
        }
    }
}

// ---------------- kernel 3: fused bisection-threshold + filter + exact top-30 ----------
__global__ void __launch_bounds__(256) select_kernel() {
    int s = blockIdx.y, i = blockIdx.x;
    int sB = s * Ls;
    int gv = sB + i;
    const float* row = g_d2 + (size_t)gv * Ls;
    const uint4* row4 = (const uint4*)row;

    __shared__ __align__(16) unsigned sbuf[Ls];     // 12.5 KB (cand u64 overlay / fallback keys)
    __shared__ int scnt;
    unsigned long long* cand = (unsigned long long*)sbuf;  // 1568 slots; CAP=1536

    int tid = threadIdx.x;   // 256
    if (tid == 0) scnt = 0;

    // load entire row into registers (flipped), coalesced
    uint4 v0 = row4[tid];
    uint4 v1 = row4[tid + 256];
    uint4 v2 = row4[tid + 512];
    uint4 v3 = make_uint4(0xffffffffu, 0xffffffffu, 0xffffffffu, 0xffffffffu);
    bool rem = (tid < 784 - 768);
    if (rem) v3 = row4[tid + 768];
    #define FL4(v) { v.x = FLIPU(v.x); v.y = FLIPU(v.y); v.z = FLIPU(v.z); v.w = FLIPU(v.w); }
    FL4(v0) FL4(v1) FL4(v2) FL4(v3)
    #undef FL4

    // one sample per thread (stride 12); cooperative value-space bisection.
    // accept any T whose sample-count is in [12, 30]:
    //   count>=12 -> expected full count ~147 (>=KN w.h.p.)
    //   count<=30 -> expected full count ~367 (<CAP w.h.p.)
    unsigned samp = FLIPU(__float_as_uint(row[tid * 12]));
    unsigned lo = 0u, hi = 0xffffffffu, T = 0u;
    bool found = false;
    #pragma unroll 1
    for (int it = 0; it < 32; it++) {
        unsigned mid = lo + ((hi - lo) >> 1);
        int c = __syncthreads_count(samp <= mid);
        if (c >= 12 && c <= 30) { T = mid; found = true; break; }
        if (c < 12) lo = mid + 1; else hi = mid - 1;
    }
    if (!found) {
        // degenerate ties: minimal T with sample-count >= 30  =>  full count >= 30 GUARANTEED
        lo = 0u; hi = 0xffffffffu;
        #pragma unroll 1
        while (lo < hi) {
            unsigned mid = lo + ((hi - lo) >> 1);
            int c = __syncthreads_count(samp <= mid);
            if (c >= 30) hi = mid; else lo = mid + 1;
        }
        T = lo;
    }

    // filter registers -> candidates
    #define FPROC(vv, base) {                                                                  \
        if (vv.x <= T) { int p = atomicAdd(&scnt, 1); if (p < CAP) cand[p] = ((unsigned long long)vv.x << 32) | (unsigned)((base));     } \
        if (vv.y <= T) { int p = atomicAdd(&scnt, 1); if (p < CAP) cand[p] = ((unsigned long long)vv.y << 32) | (unsigned)((base) + 1); } \
        if (vv.z <= T) { int p = atomicAdd(&scnt, 1); if (p < CAP) cand[p] = ((unsigned long long)vv.z << 32) | (unsigned)((base) + 2); } \
        if (vv.w <= T) { int p = atomicAdd(&scnt, 1); if (p < CAP) cand[p] = ((unsigned long long)vv.w << 32) | (unsigned)((base) + 3); } \
    }
    FPROC(v0, tid * 4)
    FPROC(v1, (tid + 256) * 4)
    FPROC(v2, (tid + 512) * 4)
    if (rem) FPROC(v3, (tid + 768) * 4)
    #undef FPROC
    __syncthreads();

    int cnt = scnt;
    int* nout = g_nbr + (size_t)gv * KN;
    int* dv = g_dvi + sB;

    if (cnt >= KN && cnt <= CAP) {
        // exact rank-select among candidates (u64 = key:idx -> reference tie order)
        for (int t = tid; t < cnt; t += 256) {
            unsigned long long K = cand[t];
            int r = 0;
            for (int j = 0; j < cnt; j++) r += (cand[j] < K);
            if (r < KN) {
                int idx = (int)(K & 0xffffffffull);
                nout[r] = idx;
                atomicAdd(&dv[idx], 1);
            }
        }
    } else {
        // ultra-rare exact fallback: full-row rank select from registers
        __syncthreads();
        *(uint4*)&sbuf[tid * 4]         = v0;
        *(uint4*)&sbuf[(tid + 256) * 4] = v1;
        *(uint4*)&sbuf[(tid + 512) * 4] = v2;
        if (rem) *(uint4*)&sbuf[(tid + 768) * 4] = v3;
        __syncthreads();
        for (int t = tid; t < Ls; t += 256) {
            unsigned ut = sbuf[t];
            int r = 0;
            for (int j = 0; j < Ls; j++) {
                unsigned uj = sbuf[j];
                r += (uj < ut) || (uj == ut && j < t);
            }
            if (r < KN) {
                nout[r] = t;
                atomicAdd(&dv[t], 1);
            }
        }
    }
}

// ---------------- kernel 4: exclusive scan of degrees (single block) ----------------
__global__ void scan_kernel() {
    __shared__ int ps[1024];
    int tid = threadIdx.x;
    int start = tid * 25;
    int sum = 0;
    for (int t = start; t < start + 25 && t < NV; t++) sum += g_dvi[t];
    ps[tid] = sum;
    __syncthreads();
    for (int off = 1; off < 1024; off <<= 1) {
        int v = (tid >= off) ? ps[tid - off] : 0;
        __syncthreads();
        ps[tid] += v;
        __syncthreads();
    }
    int excl = (tid == 0) ? 0 : ps[tid - 1];
    for (int t = start; t < start + 25 && t < NV; t++) {
        g_off[t] = excl;
        excl += g_dvi[t];
    }
}

// ---------------- kernel 5: CSR fill (warp per edge) ----------------
__global__ void fill_kernel() {
    int s = blockIdx.y;
    int e = blockIdx.x * 8 + (threadIdx.x >> 5);
    int lane = threadIdx.x & 31;
    int ge = s * Ls + e;
    if (lane < KN) {
        int v  = g_nbr[(size_t)ge * KN + lane];
        int gv = s * Ls + v;
        int pos = atomicAdd(&g_cnt[gv], 1);
        g_adj[g_off[gv] + pos] = ge;
    }
}

// ---------------- kernel 6: theta1 + BN ----------------
__global__ void theta1_kernel(const float* __restrict__ x, const float* __restrict__ w1,
                              const float* __restrict__ b1, const float* __restrict__ g1,
                              const float* __restrict__ be1) {
    __shared__ float ws[Cn * HID];
    int tid = threadIdx.x;
    for (int t = tid; t < Cn * HID; t += 256) ws[t] = w1[t];
    __syncthreads();
    int gv = blockIdx.x * 8 + (tid >> 5);
    int lane = tid & 31;
    const float* f = x + (size_t)gv * Cn;
    float f0 = f[lane], f1 = f[lane + 32];
    float acc = 0.f;
    #pragma unroll
    for (int c = 0; c < 32; c++) acc = fmaf(__shfl_sync(0xffffffffu, f0, c), ws[c * HID + lane], acc);
    #pragma unroll
    for (int c = 0; c < 32; c++) acc = fmaf(__shfl_sync(0xffffffffu, f1, c), ws[(c + 32) * HID + lane], acc);
    g_h1[(size_t)gv * HID + lane] = (acc + b1[lane]) * (g1[lane] * BN_SCALE) + be1[lane];
}

// ---------------- kernel 7: v2e mean, conv1 ----------------
__global__ void v2e1_kernel() {
    int s = blockIdx.y;
    int e = blockIdx.x * 8 + (threadIdx.x >> 5);
    int lane = threadIdx.x & 31;
    int ge = s * Ls + e;
    const int* nb = g_nbr + (size_t)ge * KN;
    int myn = (lane < KN) ? nb[lane] : 0;
    const float* h = g_h1 + (size_t)s * Ls * HID;
    float acc = 0.f;
    #pragma unroll
    for (int j = 0; j < KN; j++) {
        int v = __shfl_sync(0xffffffffu, myn, j);
        acc += h[(size_t)v * HID + lane];
    }
    g_y1[(size_t)ge * HID + lane] = acc * (1.f / KN);
}

// ---------------- kernel 8: e2v mean + relu, conv1 ----------------
__global__ void e2v1_kernel() {
    int gv = blockIdx.x * 8 + (threadIdx.x >> 5);
    int lane = threadIdx.x & 31;
    int cnt = g_dvi[gv];
    int off = g_off[gv];
    float acc = 0.f;
    for (int t = 0; t < cnt; t++) {
        int ge = g_adj[off + t];
        acc += g_y1[(size_t)ge * HID + lane];
    }
    float d = fmaxf((float)cnt, 1.f);
    g_o1[(size_t)gv * HID + lane] = fmaxf(acc / d, 0.f);
}

// ---------------- kernel 9: theta2 + BN ----------------
__global__ void theta2_kernel(const float* __restrict__ w2, const float* __restrict__ b2,
                              const float* __restrict__ g2, const float* __restrict__ be2) {
    __shared__ float ws[HID * Cn];
    int tid = threadIdx.x;
    for (int t = tid; t < HID * Cn; t += 256) ws[t] = w2[t];
    __syncthreads();
    int gv = blockIdx.x * 8 + (tid >> 5);
    int lane = tid & 31;
    float f0 = g_o1[(size_t)gv * HID + lane];
    float a0 = 0.f, a1 = 0.f;
    #pragma unroll
    for (int c = 0; c < 32; c++) {
        float in = __shfl_sync(0xffffffffu, f0, c);
        a0 = fmaf(in, ws[c * Cn + lane], a0);
        a1 = fmaf(in, ws[c * Cn + lane + 32], a1);
    }
    g_h2[(size_t)gv * Cn + lane]      = (a0 + b2[lane])      * (g2[lane]      * BN_SCALE) + be2[lane];
    g_h2[(size_t)gv * Cn + lane + 32] = (a1 + b2[lane + 32]) * (g2[lane + 32] * BN_SCALE) + be2[lane + 32];
}

// ---------------- kernel 10: v2e mean, conv2 ----------------
__global__ void v2e2_kernel() {
    int s = blockIdx.y;
    int e = blockIdx.x * 8 + (threadIdx.x >> 5);
    int lane = threadIdx.x & 31;
    int ge = s * Ls + e;
    const int* nb = g_nbr + (size_t)ge * KN;
    int myn = (lane < KN) ? nb[lane] : 0;
    const float* h = g_h2 + (size_t)s * Ls * Cn;
    float a0 = 0.f, a1 = 0.f;
    #pragma unroll
    for (int j = 0; j < KN; j++) {
        int v = __shfl_sync(0xffffffffu, myn, j);
        const float* hv = h + (size_t)v * Cn;
        a0 += hv[lane];
        a1 += hv[lane + 32];
    }
    g_y2[(size_t)ge * Cn + lane]      = a0 * (1.f / KN);
    g_y2[(size_t)ge * Cn + lane + 32] = a1 * (1.f / KN);
}

// ---------------- kernel 11: e2v mean, conv2 -> output ----------------
__global__ void e2v2_kernel(float* __restrict__ out) {
    int gv = blockIdx.x * 8 + (threadIdx.x >> 5);
    int lane = threadIdx.x & 31;
    int cnt = g_dvi[gv];
    int off = g_off[gv];
    float a0 = 0.f, a1 = 0.f;
    for (int t = 0; t < cnt; t++) {
        int ge = g_adj[off + t];
        const float* y = g_y2 + (size_t)ge * Cn;
        a0 += y[lane];
        a1 += y[lane + 32];
    }
    float d = fmaxf((float)cnt, 1.f);
    out[(size_t)gv * Cn + lane]      = a0 / d;
    out[(size_t)gv * Cn + lane + 32] = a1 / d;
}

// ---------------- launch ----------------
extern "C" void kernel_launch(void* const* d_in, const int* in_sizes, int n_in,
                              void* d_out, int out_size) {
    const float* x   = (const float*)d_in[0];
    const float* w1  = (const float*)d_in[1];
    const float* b1  = (const float*)d_in[2];
    const float* g1  = (const float*)d_in[3];
    const float* be1 = (const float*)d_in[4];
    const float* w2  = (const float*)d_in[5];
    const float* b2  = (const float*)d_in[6];
    const float* g2  = (const float*)d_in[7];
    const float* be2 = (const float*)d_in[8];
    float* out = (float*)d_out;

    sq_kernel<<<NV / 8, 256>>>(x);
    dist_kernel<<<dim3(Ls / 64, Ls / 64, Bn), 64>>>(x);
    select_kernel<<<dim3(Ls, Bn), 256>>>();
    scan_kernel<<<1, 1024>>>();
    fill_kernel<<<dim3(Ls / 8, Bn), 256>>>();
    theta1_kernel<<<NV / 8, 256>>>(x, w1, b1, g1, be1);
    v2e1_kernel<<<dim3(Ls / 8, Bn), 256>>>();
    e2v1_kernel<<<NV / 8, 256>>>();
    theta2_kernel<<<NV / 8, 256>>>(w2, b2, g2, be2);
    v2e2_kernel<<<dim3(Ls / 8, Bn), 256>>>();
    e2v2_kernel<<<NV / 8, 256>>>(out);
}

// round 8
// speedup vs baseline: 2.4576x; 1.1929x over previous
#include <cuda_runtime.h>
#include <cfloat>
#include <cstdint>

#define Bn  8
#define Ls  3136      // 56*56
#define Cn  64
#define HID 32
#define KN  30
#define NV  (Bn*Ls)   // 25088 global vertices/edges
#define CAP 1536      // candidate capacity (sbuf holds 1568 u64)

// ---------------- device scratch (static globals; no allocations) ----------------
__device__ float    g_sq  [NV];
__device__ float    g_d2  [(size_t)Bn*Ls*Ls];   // 314.7 MB distance matrices
__device__ int      g_nbr [(size_t)NV*KN];      // per-edge neighbor lists (sample-local idx)
__device__ int      g_dvi [NV];                 // vertex in-degree (counts)
__device__ int      g_off [NV];                 // CSR offsets
__device__ int      g_cnt [NV];                 // CSR fill cursors
__device__ int      g_adj [(size_t)NV*KN];      // CSR: edges incident to each vertex
__device__ float    g_h1  [(size_t)NV*HID];
__device__ float    g_y1  [(size_t)NV*HID];
__device__ float    g_o1  [(size_t)NV*HID];
__device__ float    g_h2  [(size_t)NV*Cn];
__device__ float    g_y2  [(size_t)NV*Cn];

#define BN_SCALE 0.99999500003749969f
#define FLIPU(u) ((u) ^ ((unsigned)(((int)(u)) >> 31) | 0x80000000u))

// ---------------- kernel 1: row squared norms + zero counters ----------------
__global__ void sq_kernel(const float* __restrict__ x) {
    int tid = threadIdx.x;
    int gv = blockIdx.x * 8 + (tid >> 5);
    int lane = tid & 31;
    const float* p = x + (size_t)gv * Cn;
    float a = p[lane] * p[lane] + p[lane + 32] * p[lane + 32];
    #pragma unroll
    for (int off = 16; off; off >>= 1) a += __shfl_down_sync(0xffffffffu, a, off);
    if (lane == 0) g_sq[gv] = a;
    int t = blockIdx.x * 256 + tid;
    if (t < NV) { g_cnt[t] = 0; g_dvi[t] = 0; }
}

// ---------------- kernel 2: d2 = sq_i + sq_j - 2*(ft @ ft^T), symmetric tiles ----------------
__global__ void __launch_bounds__(64) dist_kernel(const float* __restrict__ x) {
    int ti = blockIdx.y, tj = blockIdx.x;
    if (ti > tj) return;
    int s = blockIdx.z;
    const float* A  = x + (size_t)s * Ls * Cn;
    float*       D  = g_d2 + (size_t)s * Ls * Ls;
    const float* sq = g_sq + s * Ls;
    int i0 = ti << 6, j0 = tj << 6;

    __shared__ __align__(16) float Ast[64][68];
    __shared__ __align__(16) float Bst[64][68];
    int tid = threadIdx.x;   // 64 threads

    for (int f = tid; f < 1024; f += 64) {
        int m = f >> 4, kq = (f & 15) << 2;
        float4 av = *(const float4*)(A + (size_t)(i0 + m) * Cn + kq);
        Ast[kq + 0][m] = av.x; Ast[kq + 1][m] = av.y; Ast[kq + 2][m] = av.z; Ast[kq + 3][m] = av.w;
        float4 bv = *(const float4*)(A + (size_t)(j0 + m) * Cn + kq);
        Bst[kq + 0][m] = bv.x; Bst[kq + 1][m] = bv.y; Bst[kq + 2][m] = bv.z; Bst[kq + 3][m] = bv.w;
    }
    __syncthreads();

    int m0 = (tid >> 3) << 3;
    int n0 = (tid & 7) << 3;
    float acc[8][8];
    #pragma unroll
    for (int r = 0; r < 8; r++)
        #pragma unroll
        for (int c = 0; c < 8; c++) acc[r][c] = 0.f;

    #pragma unroll 8
    for (int k = 0; k < 64; k++) {
        float a[8], b[8];
        *(float4*)(a)     = *(const float4*)&Ast[k][m0];
        *(float4*)(a + 4) = *(const float4*)&Ast[k][m0 + 4];
        *(float4*)(b)     = *(const float4*)&Bst[k][n0];
        *(float4*)(b + 4) = *(const float4*)&Bst[k][n0 + 4];
        #pragma unroll
        for (int r = 0; r < 8; r++)
            #pragma unroll
            for (int c = 0; c < 8; c++) acc[r][c] = fmaf(a[r], b[c], acc[r][c]);
    }

    float sqj[8], sqi[8];
    #pragma unroll
    for (int c = 0; c < 8; c++) sqj[c] = sq[j0 + n0 + c];
    #pragma unroll
    for (int r = 0; r < 8; r++) sqi[r] = sq[i0 + m0 + r];
    #pragma unroll
    for (int r = 0; r < 8; r++)
        #pragma unroll
        for (int c = 0; c < 8; c++) acc[r][c] = sqi[r] + sqj[c] - 2.f * acc[r][c];

    #pragma unroll
    for (int r = 0; r < 8; r++) {
        float* drow = D + (size_t)(i0 + m0 + r) * Ls + j0 + n0;
        *(float4*)(drow)     = make_float4(acc[r][0], acc[r][1], acc[r][2], acc[r][3]);
        *(float4*)(drow + 4) = make_float4(acc[r][4], acc[r][5], acc[r][6], acc[r][7]);
    }
    if (ti != tj) {
        #pragma unroll
        for (int c = 0; c < 8; c++) {
            float* drow = D + (size_t)(j0 + n0 + c) * Ls + i0 + m0;
            *(float4*)(drow)     = make_float4(acc[0][c], acc[1][c], acc[2][c], acc[3][c]);
            *(float4*)(drow + 4) = make_float4(acc[4][c], acc[5][c], acc[6][c], acc[7][c]);
        }
    }
}

// ---------------- kernel 3: fused bisection-threshold + filter + exact top-30 ----------
__global__ void __launch_bounds__(256) select_kernel() {
    int s = blockIdx.y, i = blockIdx.x;
    int sB = s * Ls;
    int gv = sB + i;
    const float* row = g_d2 + (size_t)gv * Ls;
    const uint4* row4 = (const uint4*)row;

    __shared__ __align__(16) unsigned sbuf[Ls];     // 12.5 KB (cand u64 overlay / fallback keys)
    __shared__ int scnt;
    unsigned long long* cand = (unsigned long long*)sbuf;  // 1568 slots; CAP=1536

    int tid = threadIdx.x;   // 256
    if (tid == 0) scnt = 0;

    // load entire row into registers (flipped), coalesced
    uint4 v0 = row4[tid];
    uint4 v1 = row4[tid + 256];
    uint4 v2 = row4[tid + 512];
    uint4 v3 = make_uint4(0xffffffffu, 0xffffffffu, 0xffffffffu, 0xffffffffu);
    bool rem = (tid < 784 - 768);
    if (rem) v3 = row4[tid + 768];
    #define FL4(v) { v.x = FLIPU(v.x); v.y = FLIPU(v.y); v.z = FLIPU(v.z); v.w = FLIPU(v.w); }
    FL4(v0) FL4(v1) FL4(v2) FL4(v3)
    #undef FL4

    // one sample per thread (stride 12); cooperative value-space bisection.
    // TIGHT acceptance window [12, 16]:
    //   count>=12 -> expected full count ~147 (>=KN w.h.p.)
    //   count<=16 -> expected full count ~200 (rank loop stays cheap)
    unsigned samp = FLIPU(__float_as_uint(row[tid * 12]));
    unsigned lo = 0u, hi = 0xffffffffu, T = 0u;
    bool found = false;
    #pragma unroll 1
    for (int it = 0; it < 34; it++) {
        unsigned mid = lo + ((hi - lo) >> 1);
        int c = __syncthreads_count(samp <= mid);
        if (c >= 12 && c <= 16) { T = mid; found = true; break; }
        if (c < 12) lo = mid + 1; else hi = mid - 1;
        if (lo > hi) break;   // window skipped by tied samples -> fallback
    }
    if (!found) {
        // degenerate: minimal T with sample-count >= 30  =>  full count >= 30 GUARANTEED
        lo = 0u; hi = 0xffffffffu;
        #pragma unroll 1
        while (lo < hi) {
            unsigned mid = lo + ((hi - lo) >> 1);
            int c = __syncthreads_count(samp <= mid);
            if (c >= 30) hi = mid; else lo = mid + 1;
        }
        T = lo;
    }

    // filter registers -> candidates
    #define FPROC(vv, base) {                                                                  \
        if (vv.x <= T) { int p = atomicAdd(&scnt, 1); if (p < CAP) cand[p] = ((unsigned long long)vv.x << 32) | (unsigned)((base));     } \
        if (vv.y <= T) { int p = atomicAdd(&scnt, 1); if (p < CAP) cand[p] = ((unsigned long long)vv.y << 32) | (unsigned)((base) + 1); } \
        if (vv.z <= T) { int p = atomicAdd(&scnt, 1); if (p < CAP) cand[p] = ((unsigned long long)vv.z << 32) | (unsigned)((base) + 2); } \
        if (vv.w <= T) { int p = atomicAdd(&scnt, 1); if (p < CAP) cand[p] = ((unsigned long long)vv.w << 32) | (unsigned)((base) + 3); } \
    }
    FPROC(v0, tid * 4)
    FPROC(v1, (tid + 256) * 4)
    FPROC(v2, (tid + 512) * 4)
    if (rem) FPROC(v3, (tid + 768) * 4)
    #undef FPROC
    __syncthreads();

    int cnt = scnt;
    int* nout = g_nbr + (size_t)gv * KN;
    int* dv = g_dvi + sB;

    if (cnt >= KN && cnt <= CAP) {
        // exact rank-select among candidates (u64 = key:idx -> reference tie order)
        for (int t = tid; t < cnt; t += 256) {
            unsigned long long K = cand[t];
            int r = 0;
            for (int j = 0; j < cnt; j++) r += (cand[j] < K);
            if (r < KN) {
                int idx = (int)(K & 0xffffffffull);
                nout[r] = idx;
                atomicAdd(&dv[idx], 1);
            }
        }
    } else {
        // ultra-rare exact fallback: full-row rank select from registers
        __syncthreads();
        *(uint4*)&sbuf[tid * 4]         = v0;
        *(uint4*)&sbuf[(tid + 256) * 4] = v1;
        *(uint4*)&sbuf[(tid + 512) * 4] = v2;
        if (rem) *(uint4*)&sbuf[(tid + 768) * 4] = v3;
        __syncthreads();
        for (int t = tid; t < Ls; t += 256) {
            unsigned ut = sbuf[t];
            int r = 0;
            for (int j = 0; j < Ls; j++) {
                unsigned uj = sbuf[j];
                r += (uj < ut) || (uj == ut && j < t);
            }
            if (r < KN) {
                nout[r] = t;
                atomicAdd(&dv[t], 1);
            }
        }
    }
}

// ---------------- kernel 4: exclusive scan of degrees (single block) ----------------
__global__ void scan_kernel() {
    __shared__ int ps[1024];
    int tid = threadIdx.x;
    int start = tid * 25;
    int sum = 0;
    for (int t = start; t < start + 25 && t < NV; t++) sum += g_dvi[t];
    ps[tid] = sum;
    __syncthreads();
    for (int off = 1; off < 1024; off <<= 1) {
        int v = (tid >= off) ? ps[tid - off] : 0;
        __syncthreads();
        ps[tid] += v;
        __syncthreads();
    }
    int excl = (tid == 0) ? 0 : ps[tid - 1];
    for (int t = start; t < start + 25 && t < NV; t++) {
        g_off[t] = excl;
        excl += g_dvi[t];
    }
}

// ---------------- kernel 5: CSR fill (warp per edge) ----------------
__global__ void fill_kernel() {
    int s = blockIdx.y;
    int e = blockIdx.x * 8 + (threadIdx.x >> 5);
    int lane = threadIdx.x & 31;
    int ge = s * Ls + e;
    if (lane < KN) {
        int v  = g_nbr[(size_t)ge * KN + lane];
        int gv = s * Ls + v;
        int pos = atomicAdd(&g_cnt[gv], 1);
        g_adj[g_off[gv] + pos] = ge;
    }
}

// ---------------- kernel 6: theta1 + BN ----------------
__global__ void theta1_kernel(const float* __restrict__ x, const float* __restrict__ w1,
                              const float* __restrict__ b1, const float* __restrict__ g1,
                              const float* __restrict__ be1) {
    __shared__ float ws[Cn * HID];
    int tid = threadIdx.x;
    for (int t = tid; t < Cn * HID; t += 256) ws[t] = w1[t];
    __syncthreads();
    int gv = blockIdx.x * 8 + (tid >> 5);
    int lane = tid & 31;
    const float* f = x + (size_t)gv * Cn;
    float f0 = f[lane], f1 = f[lane + 32];
    float acc = 0.f;
    #pragma unroll
    for (int c = 0; c < 32; c++) acc = fmaf(__shfl_sync(0xffffffffu, f0, c), ws[c * HID + lane], acc);
    #pragma unroll
    for (int c = 0; c < 32; c++) acc = fmaf(__shfl_sync(0xffffffffu, f1, c), ws[(c + 32) * HID + lane], acc);
    g_h1[(size_t)gv * HID + lane] = (acc + b1[lane]) * (g1[lane] * BN_SCALE) + be1[lane];
}

// ---------------- kernel 7: v2e mean, conv1 ----------------
__global__ void v2e1_kernel() {
    int s = blockIdx.y;
    int e = blockIdx.x * 8 + (threadIdx.x >> 5);
    int lane = threadIdx.x & 31;
    int ge = s * Ls + e;
    const int* nb = g_nbr + (size_t)ge * KN;
    int myn = (lane < KN) ? nb[lane] : 0;
    const float* h = g_h1 + (size_t)s * Ls * HID;
    float acc = 0.f;
    #pragma unroll
    for (int j = 0; j < KN; j++) {
        int v = __shfl_sync(0xffffffffu, myn, j);
        acc += h[(size_t)v * HID + lane];
    }
    g_y1[(size_t)ge * HID + lane] = acc * (1.f / KN);
}

// ---------------- kernel 8: e2v mean + relu, conv1 ----------------
__global__ void e2v1_kernel() {
    int gv = blockIdx.x * 8 + (threadIdx.x >> 5);
    int lane = threadIdx.x & 31;
    int cnt = g_dvi[gv];
    int off = g_off[gv];
    float acc = 0.f;
    for (int t = 0; t < cnt; t++) {
        int ge = g_adj[off + t];
        acc += g_y1[(size_t)ge * HID + lane];
    }
    float d = fmaxf((float)cnt, 1.f);
    g_o1[(size_t)gv * HID + lane] = fmaxf(acc / d, 0.f);
}

// ---------------- kernel 9: theta2 + BN ----------------
__global__ void theta2_kernel(const float* __restrict__ w2, const float* __restrict__ b2,
                              const float* __restrict__ g2, const float* __restrict__ be2) {
    __shared__ float ws[HID * Cn];
    int tid = threadIdx.x;
    for (int t = tid; t < HID * Cn; t += 256) ws[t] = w2[t];
    __syncthreads();
    int gv = blockIdx.x * 8 + (tid >> 5);
    int lane = tid & 31;
    float f0 = g_o1[(size_t)gv * HID + lane];
    float a0 = 0.f, a1 = 0.f;
    #pragma unroll
    for (int c = 0; c < 32; c++) {
        float in = __shfl_sync(0xffffffffu, f0, c);
        a0 = fmaf(in, ws[c * Cn + lane], a0);
        a1 = fmaf(in, ws[c * Cn + lane + 32], a1);
    }
    g_h2[(size_t)gv * Cn + lane]      = (a0 + b2[lane])      * (g2[lane]      * BN_SCALE) + be2[lane];
    g_h2[(size_t)gv * Cn + lane + 32] = (a1 + b2[lane + 32]) * (g2[lane + 32] * BN_SCALE) + be2[lane + 32];
}

// ---------------- kernel 10: v2e mean, conv2 ----------------
__global__ void v2e2_kernel() {
    int s = blockIdx.y;
    int e = blockIdx.x * 8 + (threadIdx.x >> 5);
    int lane = threadIdx.x & 31;
    int ge = s * Ls + e;
    const int* nb = g_nbr + (size_t)ge * KN;
    int myn = (lane < KN) ? nb[lane] : 0;
    const float* h = g_h2 + (size_t)s * Ls * Cn;
    float a0 = 0.f, a1 = 0.f;
    #pragma unroll
    for (int j = 0; j < KN; j++) {
        int v = __shfl_sync(0xffffffffu, myn, j);
        const float* hv = h + (size_t)v * Cn;
        a0 += hv[lane];
        a1 += hv[lane + 32];
    }
    g_y2[(size_t)ge * Cn + lane]      = a0 * (1.f / KN);
    g_y2[(size_t)ge * Cn + lane + 32] = a1 * (1.f / KN);
}

// ---------------- kernel 11: e2v mean, conv2 -> output ----------------
__global__ void e2v2_kernel(float* __restrict__ out) {
    int gv = blockIdx.x * 8 + (threadIdx.x >> 5);
    int lane = threadIdx.x & 31;
    int cnt = g_dvi[gv];
    int off = g_off[gv];
    float a0 = 0.f, a1 = 0.f;
    for (int t = 0; t < cnt; t++) {
        int ge = g_adj[off + t];
        const float* y = g_y2 + (size_t)ge * Cn;
        a0 += y[lane];
        a1 += y[lane + 32];
    }
    float d = fmaxf((float)cnt, 1.f);
    out[(size_t)gv * Cn + lane]      = a0 / d;
    out[(size_t)gv * Cn + lane + 32] = a1 / d;
}

// ---------------- launch ----------------
extern "C" void kernel_launch(void* const* d_in, const int* in_sizes, int n_in,
                              void* d_out, int out_size) {
    const float* x   = (const float*)d_in[0];
    const float* w1  = (const float*)d_in[1];
    const float* b1  = (const float*)d_in[2];
    const float* g1  = (const float*)d_in[3];
    const float* be1 = (const float*)d_in[4];
    const float* w2  = (const float*)d_in[5];
    const float* b2  = (const float*)d_in[6];
    const float* g2  = (const float*)d_in[7];
    const float* be2 = (const float*)d_in[8];
    float* out = (float*)d_out;

    sq_kernel<<<NV / 8, 256>>>(x);
    dist_kernel<<<dim3(Ls / 64, Ls / 64, Bn), 64>>>(x);
    select_kernel<<<dim3(Ls, Bn), 256>>>();
    scan_kernel<<<1, 1024>>>();
    fill_kernel<<<dim3(Ls / 8, Bn), 256>>>();
    theta1_kernel<<<NV / 8, 256>>>(x, w1, b1, g1, be1);
    v2e1_kernel<<<dim3(Ls / 8, Bn), 256>>>();
    e2v1_kernel<<<NV / 8, 256>>>();
    theta2_kernel<<<NV / 8, 256>>>(w2, b2, g2, be2);
    v2e2_kernel<<<dim3(Ls / 8, Bn), 256>>>();
    e2v2_kernel<<<NV / 8, 256>>>(out);
}